// round 7
// baseline (speedup 1.0000x reference)
#include <cuda_runtime.h>
#include <cstdint>
#include <math_constants.h>

#define BM   64
#define BN   64
#define DK   64
#define SLEN 1024
#define QLEN 1024
#define NBH  32
#define NTILE (SLEN / BN)
#define KVSTRIDE 72      // K/V tile row stride (words): conflict-free B-frag LDS
#define PSSTRIDE 68      // prev/S/P tile row stride (words): conflict-free A-frag LDS

#define KVTILE (64 * KVSTRIDE)     // 4608 words
#define PSTILE (64 * PSSTRIDE)     // 4352 words
#define DYN_WORDS (2 * (KVTILE + PSTILE))
#define DYN_BYTES (DYN_WORDS * 4)  // 71680 B -> 3 CTAs/SM

__device__ __forceinline__ uint32_t f2tf(float x) {
    uint32_t r; asm("cvt.rna.tf32.f32 %0, %1;" : "=r"(r) : "f"(x)); return r;
}

__device__ __forceinline__ void mma_tf32(float c[4],
    uint32_t a0, uint32_t a1, uint32_t a2, uint32_t a3,
    uint32_t b0, uint32_t b1)
{
    asm volatile(
        "mma.sync.aligned.m16n8k8.row.col.f32.tf32.tf32.f32 "
        "{%0,%1,%2,%3}, {%4,%5,%6,%7}, {%8,%9}, {%0,%1,%2,%3};"
        : "+f"(c[0]), "+f"(c[1]), "+f"(c[2]), "+f"(c[3])
        : "r"(a0), "r"(a1), "r"(a2), "r"(a3), "r"(b0), "r"(b1));
}

__device__ __forceinline__ void cp16(uint32_t saddr, const void* g) {
    asm volatile("cp.async.cg.shared.global [%0], [%1], 16;" :: "r"(saddr), "l"(g));
}

// One combined prefetch group: a 64x64 K/V tile (stride KVSTRIDE) and a
// 64x64 prev/S tile (stride PSSTRIDE). 8 x 16B per thread, single commit.
__device__ __forceinline__ void stage_async(uint32_t kv_s, const float* gkv, int gkv_stride,
                                            uint32_t ps_s, const float* gps, int tid)
{
    #pragma unroll
    for (int i = 0; i < 4; i++) {
        int id  = tid + i * 256;
        int row = id >> 4, cc = (id & 15) << 2;
        cp16(kv_s + (uint32_t)(row * KVSTRIDE + cc) * 4,
             gkv + (size_t)row * gkv_stride + cc);
    }
    #pragma unroll
    for (int i = 0; i < 4; i++) {
        int id  = tid + i * 256;
        int row = id >> 4, cc = (id & 15) << 2;
        cp16(ps_s + (uint32_t)(row * PSSTRIDE + cc) * 4,
             gps + (size_t)row * SLEN + cc);
    }
    asm volatile("cp.async.commit_group;");
}

__global__ void __launch_bounds__(256, 3)
attn_kernel(const float* __restrict__ q, const float* __restrict__ k,
            const float* __restrict__ v, const float* __restrict__ prev,
            const float* __restrict__ scale_p,
            float* __restrict__ outO, float* __restrict__ outW,
            float* __restrict__ outS)
{
    extern __shared__ float dyn[];
    float* kvb[2] = { dyn,               dyn + KVTILE };
    float* psb[2] = { dyn + 2 * KVTILE,  dyn + 2 * KVTILE + PSTILE };
    __shared__ float rowmax[BM], rowinv[BM];
    __shared__ float pm[BM][2], pl[BM][2];

    const int tid  = threadIdx.x;
    const int bh   = blockIdx.y;
    const int m0   = blockIdx.x * BM;
    const int warp = tid >> 5, lane = tid & 31;
    const int g    = lane >> 2, t4 = lane & 3;
    const int wm   = warp & 3;
    const int wn   = warp >> 2;
    const float scale = scale_p[0];

    const float* qb = q    + ((size_t)bh * QLEN + m0) * DK;
    const float* kb = k    + (size_t)bh * DK * SLEN;
    const float* vb = v    + (size_t)bh * SLEN * DK;
    const float* pb = prev + ((size_t)bh * QLEN + m0) * SLEN;
    float* sb = outS + ((size_t)bh * QLEN + m0) * SLEN;
    float* wb = outW + ((size_t)bh * QLEN + m0) * SLEN;
    float* ob = outO + ((size_t)bh * QLEN + m0) * DK;

    uint32_t kv_s[2], ps_s[2];
    kv_s[0] = (uint32_t)__cvta_generic_to_shared(kvb[0]);
    kv_s[1] = (uint32_t)__cvta_generic_to_shared(kvb[1]);
    ps_s[0] = (uint32_t)__cvta_generic_to_shared(psb[0]);
    ps_s[1] = (uint32_t)__cvta_generic_to_shared(psb[1]);

    const int r0 = wm * 16 + g, r1 = r0 + 8;
    const int bcol = wn * 32 + g;

    // prologue A: stage 0 (K tile 0 + prev tile 0)
    stage_async(kv_s[0], kb, SLEN, ps_s[0], pb, tid);

    // ---- Q fragments into registers (rounded tf32, scale folded) ----
    uint32_t qa[8][4];
    {
        const float* q0 = qb + (size_t)r0 * DK;
        const float* q1 = qb + (size_t)r1 * DK;
        #pragma unroll
        for (int ks = 0; ks < 8; ks++) {
            qa[ks][0] = f2tf(q0[ks * 8 + t4]     * scale);
            qa[ks][1] = f2tf(q1[ks * 8 + t4]     * scale);
            qa[ks][2] = f2tf(q0[ks * 8 + t4 + 4] * scale);
            qa[ks][3] = f2tf(q1[ks * 8 + t4 + 4] * scale);
        }
    }

    // ======== Phase A: S = Q@K + prev -> gmem, online row max/sum ========
    float m0r = -CUDART_INF_F, m1r = -CUDART_INF_F, l0r = 0.f, l1r = 0.f;

    #pragma unroll 1
    for (int st = 0; st < NTILE; st++) {
        const int cur = st & 1;
        if (st + 1 < NTILE) {
            stage_async(kv_s[cur ^ 1], kb + (st + 1) * BN, SLEN,
                        ps_s[cur ^ 1], pb + (st + 1) * BN, tid);
            asm volatile("cp.async.wait_group 1;");
        } else {
            asm volatile("cp.async.wait_group 0;");
        }
        __syncthreads();

        const float* Kc = kvb[cur];
        float acc[4][4] = {};
        #pragma unroll
        for (int ks = 0; ks < 8; ks++) {
            #pragma unroll
            for (int nt = 0; nt < 4; nt++) {
                uint32_t b0 = f2tf(Kc[(ks * 8 + t4    ) * KVSTRIDE + bcol + nt * 8]);
                uint32_t b1 = f2tf(Kc[(ks * 8 + t4 + 4) * KVSTRIDE + bcol + nt * 8]);
                mma_tf32(acc[nt], qa[ks][0], qa[ks][1], qa[ks][2], qa[ks][3], b0, b1);
            }
        }

        // epilogue: prev from smem, add, write S, online stats
        const float* Pv = psb[cur];
        #pragma unroll
        for (int nt = 0; nt < 4; nt++) {
            int c = wn * 32 + nt * 8 + 2 * t4;
            float2 p0 = *(const float2*)(Pv + r0 * PSSTRIDE + c);
            float2 p1 = *(const float2*)(Pv + r1 * PSSTRIDE + c);
            acc[nt][0] += p0.x; acc[nt][1] += p0.y;
            acc[nt][2] += p1.x; acc[nt][3] += p1.y;
            int col = st * BN + c;
            *(float2*)(sb + (size_t)r0 * SLEN + col) = make_float2(acc[nt][0], acc[nt][1]);
            *(float2*)(sb + (size_t)r1 * SLEN + col) = make_float2(acc[nt][2], acc[nt][3]);
        }
        float tm0 = acc[0][0], tm1 = acc[0][2];
        #pragma unroll
        for (int nt = 0; nt < 4; nt++) {
            tm0 = fmaxf(tm0, fmaxf(acc[nt][0], acc[nt][1]));
            tm1 = fmaxf(tm1, fmaxf(acc[nt][2], acc[nt][3]));
        }
        float nm0 = fmaxf(m0r, tm0), nm1 = fmaxf(m1r, tm1);
        float e0 = 0.f, e1 = 0.f;
        #pragma unroll
        for (int nt = 0; nt < 4; nt++) {
            e0 += __expf(acc[nt][0] - nm0) + __expf(acc[nt][1] - nm0);
            e1 += __expf(acc[nt][2] - nm1) + __expf(acc[nt][3] - nm1);
        }
        l0r = l0r * __expf(m0r - nm0) + e0;
        l1r = l1r * __expf(m1r - nm1) + e1;
        m0r = nm0; m1r = nm1;

        __syncthreads();
    }

    // ---- cross-thread softmax stat reduction ----
    #pragma unroll
    for (int off = 1; off <= 2; off <<= 1) {
        float om = __shfl_xor_sync(0xffffffffu, m0r, off);
        float ol = __shfl_xor_sync(0xffffffffu, l0r, off);
        float nm = fmaxf(m0r, om);
        l0r = l0r * __expf(m0r - nm) + ol * __expf(om - nm);
        m0r = nm;
        om = __shfl_xor_sync(0xffffffffu, m1r, off);
        ol = __shfl_xor_sync(0xffffffffu, l1r, off);
        nm = fmaxf(m1r, om);
        l1r = l1r * __expf(m1r - nm) + ol * __expf(om - nm);
        m1r = nm;
    }
    if (t4 == 0) {
        pm[r0][wn] = m0r; pl[r0][wn] = l0r;
        pm[r1][wn] = m1r; pl[r1][wn] = l1r;
    }
    __syncthreads();
    if (tid < BM) {
        float ma = pm[tid][0], mb = pm[tid][1];
        float nm = fmaxf(ma, mb);
        float l  = pl[tid][0] * __expf(ma - nm) + pl[tid][1] * __expf(mb - nm);
        rowmax[tid] = nm;
        rowinv[tid] = 1.f / l;
    }
    __syncthreads();

    // ======== Phase B (reverse order): P = softmax(S) -> gmem; O += P @ V ====
    float acc2[4][4] = {};
    // prologue B: stage for tile 15 (V tile + S tile via cp.async)
    stage_async(kv_s[(NTILE - 1) & 1], vb + (size_t)(NTILE - 1) * BN * DK, DK,
                ps_s[(NTILE - 1) & 1], sb + (NTILE - 1) * BN, tid);

    #pragma unroll 1
    for (int st = NTILE - 1; st >= 0; st--) {
        const int cur = st & 1;
        if (st > 0) {
            stage_async(kv_s[cur ^ 1], vb + (size_t)(st - 1) * BN * DK, DK,
                        ps_s[cur ^ 1], sb + (st - 1) * BN, tid);
            asm volatile("cp.async.wait_group 1;");
        } else {
            asm volatile("cp.async.wait_group 0;");
        }

        // exp pass on OWN cp.async chunks (no barrier needed before this):
        // read S from smem, write P to gmem, store tf32 P back in place.
        float* Ps = psb[cur];
        #pragma unroll
        for (int i = 0; i < 4; i++) {
            int id  = tid + i * 256;
            int row = id >> 4, c4 = (id & 15) << 2;
            float4 x = *(const float4*)(Ps + row * PSSTRIDE + c4);
            float mr = rowmax[row], il = rowinv[row];
            float4 p;
            p.x = __expf(x.x - mr) * il;
            p.y = __expf(x.y - mr) * il;
            p.z = __expf(x.z - mr) * il;
            p.w = __expf(x.w - mr) * il;
            *(float4*)(wb + (size_t)row * SLEN + st * BN + c4) = p;
            uint4 w4;
            w4.x = f2tf(p.x); w4.y = f2tf(p.y); w4.z = f2tf(p.z); w4.w = f2tf(p.w);
            *(uint4*)(Ps + row * PSSTRIDE + c4) = w4;
        }
        __syncthreads();   // everyone's P frags + V chunks visible

        const uint32_t* Pu = (const uint32_t*)psb[cur];
        const float*    Vc = kvb[cur];
        #pragma unroll
        for (int ks = 0; ks < 8; ks++) {
            uint32_t a0 = Pu[r0 * PSSTRIDE + ks * 8 + t4];
            uint32_t a1 = Pu[r1 * PSSTRIDE + ks * 8 + t4];
            uint32_t a2 = Pu[r0 * PSSTRIDE + ks * 8 + t4 + 4];
            uint32_t a3 = Pu[r1 * PSSTRIDE + ks * 8 + t4 + 4];
            #pragma unroll
            for (int nt = 0; nt < 4; nt++) {
                uint32_t b0 = f2tf(Vc[(ks * 8 + t4    ) * KVSTRIDE + bcol + nt * 8]);
                uint32_t b1 = f2tf(Vc[(ks * 8 + t4 + 4) * KVSTRIDE + bcol + nt * 8]);
                mma_tf32(acc2[nt], a0, a1, a2, a3, b0, b1);
            }
        }
        __syncthreads();
    }

    // ---- write O ----
    #pragma unroll
    for (int nt = 0; nt < 4; nt++) {
        int col = wn * 32 + nt * 8 + 2 * t4;
        *(float2*)(ob + (size_t)r0 * DK + col) = make_float2(acc2[nt][0], acc2[nt][1]);
        *(float2*)(ob + (size_t)r1 * DK + col) = make_float2(acc2[nt][2], acc2[nt][3]);
    }
}

extern "C" void kernel_launch(void* const* d_in, const int* in_sizes, int n_in,
                              void* d_out, int out_size)
{
    const float* q     = (const float*)d_in[0];
    const float* k     = (const float*)d_in[1];
    const float* v     = (const float*)d_in[2];
    const float* prev  = (const float*)d_in[3];
    const float* scale = (const float*)d_in[4];

    float* out  = (float*)d_out;
    float* outO = out;                                   // [2,16,1024,64]
    float* outW = out + (size_t)NBH * QLEN * DK;         // [2,16,1024,1024]
    float* outS = outW + (size_t)NBH * QLEN * SLEN;      // [2,16,1024,1024]

    cudaFuncSetAttribute(attn_kernel,
                         cudaFuncAttributeMaxDynamicSharedMemorySize, DYN_BYTES);
    dim3 grid(QLEN / BM, NBH);
    attn_kernel<<<grid, 256, DYN_BYTES>>>(q, k, v, prev, scale, outO, outW, outS);
}

// round 8
// speedup vs baseline: 1.1387x; 1.1387x over previous
#include <cuda_runtime.h>
#include <cstdint>
#include <math_constants.h>

#define BM   64
#define BN   64
#define DK   64
#define SLEN 1024
#define QLEN 1024
#define NBH  32
#define NTILE (SLEN / BN)
#define KVSTRIDE 72      // K/V tile row stride (words): conflict-free scalar B-frag LDS
#define PSTRIDE  68      // tf32 P tile row stride (words): conflict-free A-frag LDS
#define QFSTRIDE 36      // per-lane Q-fragment block stride (words)

#define KV_WORDS (2 * 64 * KVSTRIDE)
#define QF_WORDS (4 * 32 * QFSTRIDE)
#define PS_WORDS (64 * PSTRIDE)
#define AB_WORDS (PS_WORDS > QF_WORDS ? PS_WORDS : QF_WORDS)
#define DYN_BYTES ((KV_WORDS + AB_WORDS) * 4)

__device__ __forceinline__ uint32_t f2tf(float x) {
    uint32_t r; asm("cvt.rna.tf32.f32 %0, %1;" : "=r"(r) : "f"(x)); return r;
}

__device__ __forceinline__ void mma_tf32(float c[4],
    uint32_t a0, uint32_t a1, uint32_t a2, uint32_t a3,
    uint32_t b0, uint32_t b1)
{
    asm volatile(
        "mma.sync.aligned.m16n8k8.row.col.f32.tf32.tf32.f32 "
        "{%0,%1,%2,%3}, {%4,%5,%6,%7}, {%8,%9}, {%0,%1,%2,%3};"
        : "+f"(c[0]), "+f"(c[1]), "+f"(c[2]), "+f"(c[3])
        : "r"(a0), "r"(a1), "r"(a2), "r"(a3), "r"(b0), "r"(b1));
}

__device__ __forceinline__ void cp16(uint32_t saddr, const void* g) {
    asm volatile("cp.async.cg.shared.global [%0], [%1], 16;" :: "r"(saddr), "l"(g));
}

// Load one 64x64 fp32 tile (row stride gstride in gmem) into smem (stride KVSTRIDE).
__device__ __forceinline__ void tile_async(uint32_t sbase, const float* gbase,
                                           int gstride, int tid)
{
    #pragma unroll
    for (int i = 0; i < 4; i++) {
        int id  = tid + i * 256;            // 1024 16B chunks
        int row = id >> 4, cc = (id & 15) << 2;
        cp16(sbase + (uint32_t)(row * KVSTRIDE + cc) * 4,
             gbase + (size_t)row * gstride + cc);
    }
    asm volatile("cp.async.commit_group;");
}

__global__ void __launch_bounds__(256, 4)
attn_kernel(const float* __restrict__ q, const float* __restrict__ k,
            const float* __restrict__ v, const float* __restrict__ prev,
            const float* __restrict__ scale_p,
            float* __restrict__ outO, float* __restrict__ outW,
            float* __restrict__ outS)
{
    extern __shared__ float dyn[];
    float*    kv = dyn;                         // 2 x 64 x KVSTRIDE fp32 (K or V)
    uint32_t* QP = (uint32_t*)(dyn + KV_WORDS); // phase A: Q frags; phase B: P tile
    __shared__ float rowmax[BM], rowinv[BM];
    __shared__ float pm[BM][2], pl[BM][2];

    const int tid  = threadIdx.x;
    const int bh   = blockIdx.y;
    const int m0   = blockIdx.x * BM;
    const int warp = tid >> 5, lane = tid & 31;
    const int g    = lane >> 2, t4 = lane & 3;
    const int wm   = warp & 3;
    const int wn   = warp >> 2;
    const float scale = scale_p[0];

    const float* qb = q    + ((size_t)bh * QLEN + m0) * DK;
    const float* kb = k    + (size_t)bh * DK * SLEN;
    const float* vb = v    + (size_t)bh * SLEN * DK;
    const float* pb = prev + ((size_t)bh * QLEN + m0) * SLEN;
    float* sb = outS + ((size_t)bh * QLEN + m0) * SLEN;
    float* wb = outW + ((size_t)bh * QLEN + m0) * SLEN;
    float* ob = outO + ((size_t)bh * QLEN + m0) * DK;

    const uint32_t kv_s = (uint32_t)__cvta_generic_to_shared(kv);
    const int r0 = wm * 16 + g, r1 = r0 + 8;
    const int bcol = wn * 32 + g;
    uint32_t* const myQ = QP + (wm * 32 + lane) * QFSTRIDE;

    tile_async(kv_s, kb, SLEN, tid);   // K tile 0 -> buf 0

    // ---- Q fragments into smem in MMA order (rounded tf32, scale folded) ----
    if (wn == 0) {
        const float* q0 = qb + (size_t)r0 * DK;
        const float* q1 = qb + (size_t)r1 * DK;
        #pragma unroll
        for (int ks = 0; ks < 8; ks++) {
            uint4 w;
            w.x = f2tf(q0[ks * 8 + t4]     * scale);
            w.y = f2tf(q1[ks * 8 + t4]     * scale);
            w.z = f2tf(q0[ks * 8 + t4 + 4] * scale);
            w.w = f2tf(q1[ks * 8 + t4 + 4] * scale);
            *(uint4*)(myQ + ks * 4) = w;
        }
    }

    // ======== Phase A: S = Q@K + prev -> gmem, online row max/sum ========
    float m0r = -CUDART_INF_F, m1r = -CUDART_INF_F, l0r = 0.f, l1r = 0.f;

    #pragma unroll 1
    for (int st = 0; st < NTILE; st++) {
        const int cur = st & 1;
        if (st + 1 < NTILE) {
            tile_async(kv_s + (uint32_t)((cur ^ 1) * 64 * KVSTRIDE) * 4,
                       kb + (st + 1) * BN, SLEN, tid);
            asm volatile("cp.async.wait_group 1;");
        } else {
            asm volatile("cp.async.wait_group 0;");
        }
        __syncthreads();

        // prefetch prev, streaming (read-once: evict-first, keep S resident in L2)
        float2 pv0[4], pv1[4];
        #pragma unroll
        for (int nt = 0; nt < 4; nt++) {
            int col = st * BN + wn * 32 + nt * 8 + 2 * t4;
            pv0[nt] = __ldcs((const float2*)(pb + (size_t)r0 * SLEN + col));
            pv1[nt] = __ldcs((const float2*)(pb + (size_t)r1 * SLEN + col));
        }

        const float* Kc = kv + cur * 64 * KVSTRIDE;
        float acc[4][4] = {};
        #pragma unroll
        for (int ks = 0; ks < 8; ks++) {
            uint4 a = *(const uint4*)(myQ + ks * 4);
            #pragma unroll
            for (int nt = 0; nt < 4; nt++) {
                uint32_t b0 = f2tf(Kc[(ks * 8 + t4    ) * KVSTRIDE + bcol + nt * 8]);
                uint32_t b1 = f2tf(Kc[(ks * 8 + t4 + 4) * KVSTRIDE + bcol + nt * 8]);
                mma_tf32(acc[nt], a.x, a.y, a.z, a.w, b0, b1);
            }
        }

        // epilogue in-place: S = acc + prev, write S (default policy: re-read soon)
        #pragma unroll
        for (int nt = 0; nt < 4; nt++) {
            int col = st * BN + wn * 32 + nt * 8 + 2 * t4;
            acc[nt][0] += pv0[nt].x; acc[nt][1] += pv0[nt].y;
            acc[nt][2] += pv1[nt].x; acc[nt][3] += pv1[nt].y;
            *(float2*)(sb + (size_t)r0 * SLEN + col) = make_float2(acc[nt][0], acc[nt][1]);
            *(float2*)(sb + (size_t)r1 * SLEN + col) = make_float2(acc[nt][2], acc[nt][3]);
        }
        float tm0 = acc[0][0], tm1 = acc[0][2];
        #pragma unroll
        for (int nt = 0; nt < 4; nt++) {
            tm0 = fmaxf(tm0, fmaxf(acc[nt][0], acc[nt][1]));
            tm1 = fmaxf(tm1, fmaxf(acc[nt][2], acc[nt][3]));
        }
        float nm0 = fmaxf(m0r, tm0), nm1 = fmaxf(m1r, tm1);
        float e0 = 0.f, e1 = 0.f;
        #pragma unroll
        for (int nt = 0; nt < 4; nt++) {
            e0 += __expf(acc[nt][0] - nm0) + __expf(acc[nt][1] - nm0);
            e1 += __expf(acc[nt][2] - nm1) + __expf(acc[nt][3] - nm1);
        }
        l0r = l0r * __expf(m0r - nm0) + e0;
        l1r = l1r * __expf(m1r - nm1) + e1;
        m0r = nm0; m1r = nm1;

        __syncthreads();
    }

    // ---- cross-thread softmax stat reduction ----
    #pragma unroll
    for (int off = 1; off <= 2; off <<= 1) {
        float om = __shfl_xor_sync(0xffffffffu, m0r, off);
        float ol = __shfl_xor_sync(0xffffffffu, l0r, off);
        float nm = fmaxf(m0r, om);
        l0r = l0r * __expf(m0r - nm) + ol * __expf(om - nm);
        m0r = nm;
        om = __shfl_xor_sync(0xffffffffu, m1r, off);
        ol = __shfl_xor_sync(0xffffffffu, l1r, off);
        nm = fmaxf(m1r, om);
        l1r = l1r * __expf(m1r - nm) + ol * __expf(om - nm);
        m1r = nm;
    }
    if (t4 == 0) {
        pm[r0][wn] = m0r; pl[r0][wn] = l0r;
        pm[r1][wn] = m1r; pl[r1][wn] = l1r;
    }
    __syncthreads();
    if (tid < BM) {
        float ma = pm[tid][0], mb = pm[tid][1];
        float nm = fmaxf(ma, mb);
        float l  = pl[tid][0] * __expf(ma - nm) + pl[tid][1] * __expf(mb - nm);
        rowmax[tid] = nm;
        rowinv[tid] = 1.f / l;
    }
    __syncthreads();

    // ======== Phase B (REVERSE tile order: S re-read is L2-hot) ========
    float acc2[4][4] = {};
    tile_async(kv_s + (uint32_t)(((NTILE - 1) & 1) * 64 * KVSTRIDE) * 4,
               vb + (size_t)(NTILE - 1) * BN * DK, DK, tid);  // V tile 15 first

    #pragma unroll 1
    for (int st = NTILE - 1; st >= 0; st--) {
        const int cur = st & 1;
        if (st > 0)
            tile_async(kv_s + (uint32_t)((cur ^ 1) * 64 * KVSTRIDE) * 4,
                       vb + (size_t)(st - 1) * BN * DK, DK, tid);

        // P tile: batched S loads (last-use: free L2 lines after the single read),
        // exp-normalize, write P streaming (never re-read), stash tf32 in smem
        {
            float4 x[4];
            int rows[4], cs[4];
            #pragma unroll
            for (int i = 0; i < 4; i++) {
                int f4  = tid + i * 256;
                rows[i] = f4 >> 4; cs[i] = (f4 & 15) << 2;
                x[i] = __ldlu((const float4*)(sb + (size_t)rows[i] * SLEN + st * BN + cs[i]));
            }
            #pragma unroll
            for (int i = 0; i < 4; i++) {
                float mr = rowmax[rows[i]], il = rowinv[rows[i]];
                float4 p;
                p.x = __expf(x[i].x - mr) * il;
                p.y = __expf(x[i].y - mr) * il;
                p.z = __expf(x[i].z - mr) * il;
                p.w = __expf(x[i].w - mr) * il;
                __stcs((float4*)(wb + (size_t)rows[i] * SLEN + st * BN + cs[i]), p);
                uint4 w4;
                w4.x = f2tf(p.x); w4.y = f2tf(p.y); w4.z = f2tf(p.z); w4.w = f2tf(p.w);
                *(uint4*)(QP + rows[i] * PSTRIDE + cs[i]) = w4;
            }
        }

        if (st > 0) asm volatile("cp.async.wait_group 1;");
        else        asm volatile("cp.async.wait_group 0;");
        __syncthreads();

        const float* Vc = kv + cur * 64 * KVSTRIDE;
        #pragma unroll
        for (int ks = 0; ks < 8; ks++) {
            uint32_t a0 = QP[r0 * PSTRIDE + ks * 8 + t4];
            uint32_t a1 = QP[r1 * PSTRIDE + ks * 8 + t4];
            uint32_t a2 = QP[r0 * PSTRIDE + ks * 8 + t4 + 4];
            uint32_t a3 = QP[r1 * PSTRIDE + ks * 8 + t4 + 4];
            #pragma unroll
            for (int nt = 0; nt < 4; nt++) {
                uint32_t b0 = f2tf(Vc[(ks * 8 + t4    ) * KVSTRIDE + bcol + nt * 8]);
                uint32_t b1 = f2tf(Vc[(ks * 8 + t4 + 4) * KVSTRIDE + bcol + nt * 8]);
                mma_tf32(acc2[nt], a0, a1, a2, a3, b0, b1);
            }
        }
        __syncthreads();
    }

    // ---- write O (streaming; never re-read) ----
    #pragma unroll
    for (int nt = 0; nt < 4; nt++) {
        int col = wn * 32 + nt * 8 + 2 * t4;
        __stcs((float2*)(ob + (size_t)r0 * DK + col), make_float2(acc2[nt][0], acc2[nt][1]));
        __stcs((float2*)(ob + (size_t)r1 * DK + col), make_float2(acc2[nt][2], acc2[nt][3]));
    }
}

extern "C" void kernel_launch(void* const* d_in, const int* in_sizes, int n_in,
                              void* d_out, int out_size)
{
    const float* q     = (const float*)d_in[0];
    const float* k     = (const float*)d_in[1];
    const float* v     = (const float*)d_in[2];
    const float* prev  = (const float*)d_in[3];
    const float* scale = (const float*)d_in[4];

    float* out  = (float*)d_out;
    float* outO = out;                                   // [2,16,1024,64]
    float* outW = out + (size_t)NBH * QLEN * DK;         // [2,16,1024,1024]
    float* outS = outW + (size_t)NBH * QLEN * SLEN;      // [2,16,1024,1024]

    cudaFuncSetAttribute(attn_kernel,
                         cudaFuncAttributeMaxDynamicSharedMemorySize, DYN_BYTES);
    dim3 grid(QLEN / BM, NBH);
    attn_kernel<<<grid, 256, DYN_BYTES>>>(q, k, v, prev, scale, outO, outW, outS);
}